// round 8
// baseline (speedup 1.0000x reference)
#include <cuda_runtime.h>

#define N_CELLS 100000
#define N_ISO   16
#define KP1     31
#define WARPS_PER_BLOCK 8
#define THREADS 256
#define BLOCKS_PER_SM 6
#define GRID    (148 * BLOCKS_PER_SM)      /* 888: one resident wave */
#define TOTAL_WARPS (GRID * WARPS_PER_BLOCK)

/* Packed 128B rows: rowS = [u, s0..s15, 0*15]; rowV = [vhat_0..vhat_16, 0*15]. */
__device__ float4       g_rowS[(size_t)N_CELLS * 8];
__device__ float4       g_rowV[(size_t)N_CELLS * 8];
__device__ float        g_partials[GRID];
__device__ unsigned int g_ticket = 0;

/* 8 threads per cell; each thread owns one 16B slice. Coalesced float4 writes.
   800000 threads = 3125 blocks x 256 exactly -> all lanes active for shfl. */
__global__ void pack_kernel(const float* __restrict__ u,
                            const float* __restrict__ s,
                            const float* __restrict__ up,
                            const float* __restrict__ sp)
{
    const int t    = blockIdx.x * blockDim.x + threadIdx.x;
    const int cell = t >> 3;
    const int r    = t & 7;
    if (cell >= N_CELLS) return;

    const size_t sb = (size_t)cell * N_ISO;
    float x0=0.f,x1=0.f,x2=0.f,x3=0.f, p0=0.f,p1=0.f,p2=0.f,p3=0.f;
    if (r == 0) {
        x0 = u[cell];  p0 = up[cell];
        x1 = s[sb+0];  p1 = sp[sb+0];
        x2 = s[sb+1];  p2 = sp[sb+1];
        x3 = s[sb+2];  p3 = sp[sb+2];
    } else if (r <= 3) {
        const int m = 4*r - 1;                   /* floats 4r..4r+3 = s[m..m+3] */
        x0 = s[sb+m];   p0 = sp[sb+m];
        x1 = s[sb+m+1]; p1 = sp[sb+m+1];
        x2 = s[sb+m+2]; p2 = sp[sb+m+2];
        x3 = s[sb+m+3]; p3 = sp[sb+m+3];
    } else if (r == 4) {
        x0 = s[sb+15];  p0 = sp[sb+15];
    }
    const float v0 = p0-x0, v1 = p1-x1, v2 = p2-x2, v3 = p3-x3;

    /* |v|^2 over the 8-lane group (slices r>=5 are zero). */
    float pv = v0*v0 + v1*v1 + v2*v2 + v3*v3;
    pv += __shfl_xor_sync(0xffffffffu, pv, 1);
    pv += __shfl_xor_sync(0xffffffffu, pv, 2);
    pv += __shfl_xor_sync(0xffffffffu, pv, 4);
    const float inv = (pv > 0.f) ? rsqrtf(pv) : 0.f;   /* |v|=0 -> vhat=0 -> cos=0 (matches ref) */

    g_rowS[(size_t)cell*8 + r] = make_float4(x0, x1, x2, x3);
    g_rowV[(size_t)cell*8 + r] = make_float4(v0*inv, v1*inv, v2*inv, v3*inv);
}

__global__ __launch_bounds__(THREADS, BLOCKS_PER_SM) void cost_kernel(
    const int* __restrict__ idx,
    float* __restrict__ out)
{
    const int warp  = threadIdx.x >> 5;
    const int lane  = threadIdx.x & 31;
    const int gwarp = blockIdx.x * WARPS_PER_BLOCK + warp;
    const int r     = lane & 7;          /* 16B slice within a 128B row */
    const int g     = lane >> 3;         /* neighbor sub-slot (0..3) per batch */

    __shared__ float ws[WARPS_PER_BLOCK];
    __shared__ int   s_islast;

    float lsum = 0.0f;

    for (int cell = gwarp; cell < N_CELLS; cell += TOTAL_WARPS) {
        /* Own row + normalized-velocity slices: broadcast lines (1 wf each). */
        const float4 a  = g_rowS[(size_t)cell * 8 + r];
        const float4 vh = g_rowV[(size_t)cell * 8 + r];
        const int ib = cell * KP1 + 1;

        float cmax = -3.0e38f;

        /* All idx loads and row gathers are independent (no shfl on the
           address path) -> ptxas front-batches them for MLP. */
        #pragma unroll
        for (int bt = 0; bt < 8; bt++) {
            const int slot = 4 * bt + g;                   /* neighbor 0..31 */
            const int sl   = (slot < KP1 - 1) ? slot : KP1 - 2;  /* clamp (compile-time for bt<7) */
            const int j    = idx[ib + sl];                 /* 4 distinct vals/warp ~1 wf, L1-hot */

            const float4 nr = g_rowS[(size_t)j * 8 + r];   /* one 128B line per row */
            const float d0 = nr.x - a.x, d1 = nr.y - a.y, d2 = nr.z - a.z, d3 = nr.w - a.w;

            float pd = vh.x*d0 + vh.y*d1 + vh.z*d2 + vh.w*d3;
            float pn = d0*d0 + d1*d1 + d2*d2 + d3*d3;

            pd += __shfl_xor_sync(0xffffffffu, pd, 1);
            pd += __shfl_xor_sync(0xffffffffu, pd, 2);
            pd += __shfl_xor_sync(0xffffffffu, pd, 4);
            pn += __shfl_xor_sync(0xffffffffu, pn, 1);
            pn += __shfl_xor_sync(0xffffffffu, pn, 2);
            pn += __shfl_xor_sync(0xffffffffu, pn, 4);

            if (r == 0 && slot < KP1 - 1) {
                const float c = (pn > 0.f) ? pd * rsqrtf(pn) : pd;  /* vn=0 -> cos=0 */
                cmax = fmaxf(cmax, c);
            }
        }

        /* Group leaders sit at lanes 0,8,16,24 -> xor8 + xor16 suffice. */
        cmax = fmaxf(cmax, __shfl_xor_sync(0xffffffffu, cmax, 8));
        cmax = fmaxf(cmax, __shfl_xor_sync(0xffffffffu, cmax, 16));

        if (lane == 0) lsum += 1.0f - cmax;
    }

    if (lane == 0) ws[warp] = lsum;
    __syncthreads();

    if (threadIdx.x == 0) {
        float bsum = 0.0f;
        #pragma unroll
        for (int w = 0; w < WARPS_PER_BLOCK; w++) bsum += ws[w];
        g_partials[blockIdx.x] = bsum;
        __threadfence();
        const unsigned t = atomicInc(&g_ticket, GRID - 1);  /* wraps -> graph-replay safe */
        s_islast = (t == GRID - 1);
    }
    __syncthreads();

    if (s_islast) {
        float psum = 0.0f;
        const volatile float* vp = g_partials;
        for (int i = threadIdx.x; i < GRID; i += THREADS) psum += vp[i];
        #pragma unroll
        for (int o = 16; o > 0; o >>= 1)
            psum += __shfl_xor_sync(0xffffffffu, psum, o);
        if (lane == 0) ws[warp] = psum;
        __syncthreads();
        if (threadIdx.x == 0) {
            float total = 0.0f;
            #pragma unroll
            for (int w = 0; w < WARPS_PER_BLOCK; w++) total += ws[w];
            out[0] = total * (1.0f / (float)N_CELLS);
        }
    }
}

extern "C" void kernel_launch(void* const* d_in, const int* in_sizes, int n_in,
                              void* d_out, int out_size) {
    const float* u   = (const float*)d_in[0];
    const float* s   = (const float*)d_in[1];
    const float* up  = (const float*)d_in[2];
    const float* sp  = (const float*)d_in[3];
    const int*   idx = (const int*)d_in[4];
    float* out = (float*)d_out;

    pack_kernel<<<(N_CELLS * 8) / THREADS, THREADS>>>(u, s, up, sp);
    cost_kernel<<<GRID, THREADS>>>(idx, out);
}

// round 9
// speedup vs baseline: 1.0999x; 1.0999x over previous
#include <cuda_runtime.h>

#define N_CELLS 100000
#define N_ISO   16
#define KP1     31
#define WARPS_PER_BLOCK 8
#define THREADS 256
#define BLOCKS_PER_SM 6
#define GRID    (148 * BLOCKS_PER_SM)      /* 888: one resident wave */
#define TOTAL_WARPS (GRID * WARPS_PER_BLOCK)
#define RSTRIDE 20                          /* smem row stride in floats (80B, 16B-aligned) */

/* Packed 128B rows: rowS = [u, s0..s15, 0*15]; rowV = [vhat_0..vhat_16, 0*15]. */
__device__ float4       g_rowS[(size_t)N_CELLS * 8];
__device__ float4       g_rowV[(size_t)N_CELLS * 8];
__device__ float        g_partials[GRID];
__device__ unsigned int g_ticket = 0;

/* 8 threads per cell; each owns one 16B slice. (From R8 — verified correct.) */
__global__ void pack_kernel(const float* __restrict__ u,
                            const float* __restrict__ s,
                            const float* __restrict__ up,
                            const float* __restrict__ sp)
{
    const int t    = blockIdx.x * blockDim.x + threadIdx.x;
    const int cell = t >> 3;
    const int r    = t & 7;
    if (cell >= N_CELLS) return;

    const size_t sb = (size_t)cell * N_ISO;
    float x0=0.f,x1=0.f,x2=0.f,x3=0.f, p0=0.f,p1=0.f,p2=0.f,p3=0.f;
    if (r == 0) {
        x0 = u[cell];  p0 = up[cell];
        x1 = s[sb+0];  p1 = sp[sb+0];
        x2 = s[sb+1];  p2 = sp[sb+1];
        x3 = s[sb+2];  p3 = sp[sb+2];
    } else if (r <= 3) {
        const int m = 4*r - 1;
        x0 = s[sb+m];   p0 = sp[sb+m];
        x1 = s[sb+m+1]; p1 = sp[sb+m+1];
        x2 = s[sb+m+2]; p2 = sp[sb+m+2];
        x3 = s[sb+m+3]; p3 = sp[sb+m+3];
    } else if (r == 4) {
        x0 = s[sb+15];  p0 = sp[sb+15];
    }
    const float v0 = p0-x0, v1 = p1-x1, v2 = p2-x2, v3 = p3-x3;

    float pv = v0*v0 + v1*v1 + v2*v2 + v3*v3;
    pv += __shfl_xor_sync(0xffffffffu, pv, 1);
    pv += __shfl_xor_sync(0xffffffffu, pv, 2);
    pv += __shfl_xor_sync(0xffffffffu, pv, 4);
    const float inv = (pv > 0.f) ? rsqrtf(pv) : 0.f;

    g_rowS[(size_t)cell*8 + r] = make_float4(x0, x1, x2, x3);
    g_rowV[(size_t)cell*8 + r] = make_float4(v0*inv, v1*inv, v2*inv, v3*inv);
}

__global__ __launch_bounds__(THREADS, BLOCKS_PER_SM) void cost_kernel(
    const int* __restrict__ idx,
    float* __restrict__ out)
{
    const int warp  = threadIdx.x >> 5;
    const int lane  = threadIdx.x & 31;
    const int gwarp = blockIdx.x * WARPS_PER_BLOCK + warp;
    const int slice = lane & 7;          /* 16B slice within a 128B packed row */
    const int rsub  = lane >> 3;         /* row sub-slot (0..3) per gather round */

    /* Per-warp staging: 32 neighbor rows (20-float stride), own a and vhat. */
    __shared__ float s_rows[WARPS_PER_BLOCK][32 * RSTRIDE];
    __shared__ float s_a  [WARPS_PER_BLOCK][RSTRIDE];
    __shared__ float s_vh [WARPS_PER_BLOCK][RSTRIDE];
    __shared__ float ws[WARPS_PER_BLOCK];
    __shared__ int   s_islast;

    float lsum = 0.0f;

    for (int cell = gwarp; cell < N_CELLS; cell += TOTAL_WARPS) {
        __syncwarp();   /* WAR: previous cell's phase-2 reads done before restage */

        /* ---- Phase 1a: stage own a and vhat (broadcast lines, 2 wf). ---- */
        {
            const int grp = lane >> 3;
            if (grp == 0) {
                const float4 v = g_rowS[(size_t)cell * 8 + slice];
                if (slice < 5) *reinterpret_cast<float4*>(&s_a[warp][slice*4]) = v;
            } else if (grp == 1) {
                const float4 v = g_rowV[(size_t)cell * 8 + slice];
                if (slice < 5) *reinterpret_cast<float4*>(&s_vh[warp][slice*4]) = v;
            }
        }

        /* ---- Phase 1b: gather 30 packed rows, 4 rows x 8 lanes per round.
           All rounds independent: no shfl, no reduce -> full MLP. ---- */
        const int ib = cell * KP1 + 1;
        #pragma unroll
        for (int t = 0; t < 8; t++) {
            const int rr = t * 4 + rsub;                 /* target row slot 0..31 */
            const int cl = (rr < KP1 - 1) ? rr : KP1 - 2;
            const int j  = idx[ib + cl];                 /* 4 distinct vals, L1-hot */
            const float4 nb = g_rowS[(size_t)j * 8 + slice];  /* 4 lines/round */
            if (slice < 5)
                *reinterpret_cast<float4*>(&s_rows[warp][rr * RSTRIDE + slice*4]) = nb;
        }
        __syncwarp();

        /* ---- Phase 2: lane l computes neighbor l serially. No shuffles. ---- */
        float pd = 0.0f, pn = 0.0f;
        #pragma unroll
        for (int k = 0; k < 5; k++) {
            const float4 nb = *reinterpret_cast<const float4*>(&s_rows[warp][lane * RSTRIDE + 4*k]);
            const float4 av = *reinterpret_cast<const float4*>(&s_a [warp][4*k]);
            const float4 vv = *reinterpret_cast<const float4*>(&s_vh[warp][4*k]);
            const float d0 = nb.x - av.x, d1 = nb.y - av.y, d2 = nb.z - av.z, d3 = nb.w - av.w;
            pd += vv.x*d0 + vv.y*d1 + vv.z*d2 + vv.w*d3;
            pn += d0*d0 + d1*d1 + d2*d2 + d3*d3;
        }

        float cosv = -3.0e38f;
        if (lane < KP1 - 1)
            cosv = (pn > 0.0f) ? pd * rsqrtf(pn) : pd;   /* vn=0 -> cos=0 (matches ref) */

        /* Warp max over 30 lanes. */
        #pragma unroll
        for (int o = 16; o > 0; o >>= 1)
            cosv = fmaxf(cosv, __shfl_xor_sync(0xffffffffu, cosv, o));

        if (lane == 0) lsum += 1.0f - cosv;
    }

    if (lane == 0) ws[warp] = lsum;
    __syncthreads();

    if (threadIdx.x == 0) {
        float bsum = 0.0f;
        #pragma unroll
        for (int w = 0; w < WARPS_PER_BLOCK; w++) bsum += ws[w];
        g_partials[blockIdx.x] = bsum;
        __threadfence();
        const unsigned t = atomicInc(&g_ticket, GRID - 1);  /* wraps -> graph-replay safe */
        s_islast = (t == GRID - 1);
    }
    __syncthreads();

    if (s_islast) {
        float psum = 0.0f;
        const volatile float* vp = g_partials;
        for (int i = threadIdx.x; i < GRID; i += THREADS) psum += vp[i];
        #pragma unroll
        for (int o = 16; o > 0; o >>= 1)
            psum += __shfl_xor_sync(0xffffffffu, psum, o);
        if (lane == 0) ws[warp] = psum;
        __syncthreads();
        if (threadIdx.x == 0) {
            float total = 0.0f;
            #pragma unroll
            for (int w = 0; w < WARPS_PER_BLOCK; w++) total += ws[w];
            out[0] = total * (1.0f / (float)N_CELLS);
        }
    }
}

extern "C" void kernel_launch(void* const* d_in, const int* in_sizes, int n_in,
                              void* d_out, int out_size) {
    const float* u   = (const float*)d_in[0];
    const float* s   = (const float*)d_in[1];
    const float* up  = (const float*)d_in[2];
    const float* sp  = (const float*)d_in[3];
    const int*   idx = (const int*)d_in[4];
    float* out = (float*)d_out;

    pack_kernel<<<(N_CELLS * 8) / THREADS, THREADS>>>(u, s, up, sp);
    cost_kernel<<<GRID, THREADS>>>(idx, out);
}

// round 10
// speedup vs baseline: 1.2607x; 1.1462x over previous
#include <cuda_runtime.h>
#include <cuda_fp16.h>

#define N_CELLS 100000
#define N_ISO   16
#define KP1     31
#define WARPS_PER_BLOCK 8
#define THREADS 256
#define BLOCKS_PER_SM 6
#define GRID    (148 * BLOCKS_PER_SM)      /* 888: one resident wave */
#define TOTAL_WARPS (GRID * WARPS_PER_BLOCK)

/* fp16 packed rows, 64B each (4 x float4): [u, s0..s15, 0*15] and [vhat_0..16, 0*15].
   float4-typed for guaranteed 16B alignment. Total 12.8MB -> L2-resident. */
__device__ float4       g_hx[(size_t)N_CELLS * 4];
__device__ float4       g_hv[(size_t)N_CELLS * 4];
__device__ float        g_partials[GRID];
__device__ unsigned int g_ticket = 0;

__device__ __forceinline__ float4 pack8h(float f0, float f1, float f2, float f3,
                                         float f4, float f5, float f6, float f7)
{
    __half2 h0 = __floats2half2_rn(f0, f1);
    __half2 h1 = __floats2half2_rn(f2, f3);
    __half2 h2 = __floats2half2_rn(f4, f5);
    __half2 h3 = __floats2half2_rn(f6, f7);
    float4 o;
    o.x = __uint_as_float(*reinterpret_cast<unsigned*>(&h0));
    o.y = __uint_as_float(*reinterpret_cast<unsigned*>(&h1));
    o.z = __uint_as_float(*reinterpret_cast<unsigned*>(&h2));
    o.w = __uint_as_float(*reinterpret_cast<unsigned*>(&h3));
    return o;
}

/* 4 threads per cell; thread r builds the 16B slice holding components 8r..8r+7
   (component 0 = u, 1..16 = s, >=17 = zero). v computed in FULL fp32 first. */
__global__ void pack_kernel(const float* __restrict__ u,
                            const float* __restrict__ s,
                            const float* __restrict__ up,
                            const float* __restrict__ sp)
{
    const int t    = blockIdx.x * blockDim.x + threadIdx.x;
    const int cell = t >> 2;
    const int r    = t & 3;
    if (cell >= N_CELLS) return;

    const size_t sb = (size_t)cell * N_ISO;
    float x[8], v[8];
    #pragma unroll
    for (int k = 0; k < 8; k++) {
        const int m = 8 * r + k;
        float xv = 0.f, pv = 0.f;
        if (m == 0)       { xv = u[cell];     pv = up[cell]; }
        else if (m <= 16) { xv = s[sb + m-1]; pv = sp[sb + m-1]; }
        x[k] = xv;
        v[k] = pv - xv;
    }

    float pvsq = 0.f;
    #pragma unroll
    for (int k = 0; k < 8; k++) pvsq += v[k]*v[k];
    pvsq += __shfl_xor_sync(0xffffffffu, pvsq, 1);
    pvsq += __shfl_xor_sync(0xffffffffu, pvsq, 2);
    const float inv = (pvsq > 0.f) ? rsqrtf(pvsq) : 0.f;  /* |v|=0 -> vhat=0 -> cos=0 (matches ref) */

    g_hx[(size_t)cell * 4 + r] = pack8h(x[0],x[1],x[2],x[3],x[4],x[5],x[6],x[7]);
    g_hv[(size_t)cell * 4 + r] = pack8h(v[0]*inv, v[1]*inv, v[2]*inv, v[3]*inv,
                                        v[4]*inv, v[5]*inv, v[6]*inv, v[7]*inv);
}

__device__ __forceinline__ void unpack8(const float4 w, float* f)
{
    unsigned a0 = __float_as_uint(w.x), a1 = __float_as_uint(w.y);
    unsigned a2 = __float_as_uint(w.z), a3 = __float_as_uint(w.w);
    float2 p;
    p = __half22float2(*reinterpret_cast<__half2*>(&a0)); f[0] = p.x; f[1] = p.y;
    p = __half22float2(*reinterpret_cast<__half2*>(&a1)); f[2] = p.x; f[3] = p.y;
    p = __half22float2(*reinterpret_cast<__half2*>(&a2)); f[4] = p.x; f[5] = p.y;
    p = __half22float2(*reinterpret_cast<__half2*>(&a3)); f[6] = p.x; f[7] = p.y;
}

__global__ __launch_bounds__(THREADS, BLOCKS_PER_SM) void cost_kernel(
    const int* __restrict__ idx,
    float* __restrict__ out)
{
    const int warp  = threadIdx.x >> 5;
    const int lane  = threadIdx.x & 31;
    const int gwarp = blockIdx.x * WARPS_PER_BLOCK + warp;
    const int r     = lane & 3;          /* 16B slice within a 64B row */
    const int nb    = lane >> 2;         /* neighbor sub-slot (0..7) per batch */

    __shared__ float ws[WARPS_PER_BLOCK];
    __shared__ int   s_islast;

    float lsum = 0.0f;

    for (int cell = gwarp; cell < N_CELLS; cell += TOTAL_WARPS) {
        /* Own slices (broadcast line) in fp32 regs; u-dim is component 0 of slice 0. */
        float a[8], vh[8];
        unpack8(g_hx[(size_t)cell * 4 + r], a);
        unpack8(g_hv[(size_t)cell * 4 + r], vh);

        const int ib = cell * KP1 + 1;
        float cmax = -3.0e38f;

        #pragma unroll
        for (int bt = 0; bt < 4; bt++) {
            const int slot = bt * 8 + nb;                      /* neighbor 0..31 */
            const int sl   = (slot < KP1 - 1) ? slot : KP1 - 2;
            const int j    = idx[ib + sl];                     /* 8 distinct/warp, L1-hot */

            /* One LDG.128 covers 8 COMPLETE rows (4 lanes x 16B each) -> ~8 lines. */
            float n[8];
            unpack8(g_hx[(size_t)j * 4 + r], n);

            float pd = 0.f, pn = 0.f;
            #pragma unroll
            for (int k = 0; k < 8; k++) {
                const float d = n[k] - a[k];
                pd = fmaf(vh[k], d, pd);
                pn = fmaf(d, d, pn);
            }

            /* Quad reduce (2 levels, within aligned groups of 4). */
            pd += __shfl_xor_sync(0xffffffffu, pd, 1);
            pd += __shfl_xor_sync(0xffffffffu, pd, 2);
            pn += __shfl_xor_sync(0xffffffffu, pn, 1);
            pn += __shfl_xor_sync(0xffffffffu, pn, 2);

            if (r == 0 && slot < KP1 - 1) {
                const float c = (pn > 0.f) ? pd * rsqrtf(pn) : 0.f;  /* vn=0 -> cos=0 */
                cmax = fmaxf(cmax, c);
            }
        }

        /* Leaders at lanes 0,4,...,28 -> xor4/8/16 completes the warp max. */
        cmax = fmaxf(cmax, __shfl_xor_sync(0xffffffffu, cmax, 4));
        cmax = fmaxf(cmax, __shfl_xor_sync(0xffffffffu, cmax, 8));
        cmax = fmaxf(cmax, __shfl_xor_sync(0xffffffffu, cmax, 16));

        if (lane == 0) lsum += 1.0f - cmax;
    }

    if (lane == 0) ws[warp] = lsum;
    __syncthreads();

    if (threadIdx.x == 0) {
        float bsum = 0.0f;
        #pragma unroll
        for (int w = 0; w < WARPS_PER_BLOCK; w++) bsum += ws[w];
        g_partials[blockIdx.x] = bsum;
        __threadfence();
        const unsigned t = atomicInc(&g_ticket, GRID - 1);  /* wraps -> graph-replay safe */
        s_islast = (t == GRID - 1);
    }
    __syncthreads();

    if (s_islast) {
        float psum = 0.0f;
        const volatile float* vp = g_partials;
        for (int i = threadIdx.x; i < GRID; i += THREADS) psum += vp[i];
        #pragma unroll
        for (int o = 16; o > 0; o >>= 1)
            psum += __shfl_xor_sync(0xffffffffu, psum, o);
        if (lane == 0) ws[warp] = psum;
        __syncthreads();
        if (threadIdx.x == 0) {
            float total = 0.0f;
            #pragma unroll
            for (int w = 0; w < WARPS_PER_BLOCK; w++) total += ws[w];
            out[0] = total * (1.0f / (float)N_CELLS);
        }
    }
}

extern "C" void kernel_launch(void* const* d_in, const int* in_sizes, int n_in,
                              void* d_out, int out_size) {
    const float* u   = (const float*)d_in[0];
    const float* s   = (const float*)d_in[1];
    const float* up  = (const float*)d_in[2];
    const float* sp  = (const float*)d_in[3];
    const int*   idx = (const int*)d_in[4];
    float* out = (float*)d_out;

    pack_kernel<<<(N_CELLS * 4 + THREADS - 1) / THREADS, THREADS>>>(u, s, up, sp);
    cost_kernel<<<GRID, THREADS>>>(idx, out);
}

// round 11
// speedup vs baseline: 1.5722x; 1.2470x over previous
#include <cuda_runtime.h>
#include <cuda_fp16.h>

#define N_CELLS 100000
#define N_ISO   16
#define KP1     31
#define WARPS_PER_BLOCK 8
#define THREADS 256
#define BLOCKS_PER_SM 6
#define GRID    (148 * BLOCKS_PER_SM)      /* 888: one resident wave */
#define TOTAL_WARPS (GRID * WARPS_PER_BLOCK)

/* fp16 packed rows, 64B each (4 x float4): [u, s0..s15, 0*15] and [vhat_0..16, 0*15]. */
__device__ float4       g_hx[(size_t)N_CELLS * 4];
__device__ float4       g_hv[(size_t)N_CELLS * 4];
__device__ float        g_partials[GRID];
__device__ unsigned int g_ticket = 0;

__device__ __forceinline__ float4 pack8h(float f0, float f1, float f2, float f3,
                                         float f4, float f5, float f6, float f7)
{
    __half2 h0 = __floats2half2_rn(f0, f1);
    __half2 h1 = __floats2half2_rn(f2, f3);
    __half2 h2 = __floats2half2_rn(f4, f5);
    __half2 h3 = __floats2half2_rn(f6, f7);
    float4 o;
    o.x = __uint_as_float(*reinterpret_cast<unsigned*>(&h0));
    o.y = __uint_as_float(*reinterpret_cast<unsigned*>(&h1));
    o.z = __uint_as_float(*reinterpret_cast<unsigned*>(&h2));
    o.w = __uint_as_float(*reinterpret_cast<unsigned*>(&h3));
    return o;
}

/* 4 threads per cell; thread r builds the 16B slice holding components 8r..8r+7
   (component 0 = u, 1..16 = s, >=17 = zero). v computed in FULL fp32 first. */
__global__ void pack_kernel(const float* __restrict__ u,
                            const float* __restrict__ s,
                            const float* __restrict__ up,
                            const float* __restrict__ sp)
{
    const int t    = blockIdx.x * blockDim.x + threadIdx.x;
    const int cell = t >> 2;
    const int r    = t & 3;
    if (cell >= N_CELLS) return;

    const size_t sb = (size_t)cell * N_ISO;
    float x[8], v[8];
    #pragma unroll
    for (int k = 0; k < 8; k++) {
        const int m = 8 * r + k;
        float xv = 0.f, pv = 0.f;
        if (m == 0)       { xv = u[cell];     pv = up[cell]; }
        else if (m <= 16) { xv = s[sb + m-1]; pv = sp[sb + m-1]; }
        x[k] = xv;
        v[k] = pv - xv;
    }

    float pvsq = 0.f;
    #pragma unroll
    for (int k = 0; k < 8; k++) pvsq += v[k]*v[k];
    pvsq += __shfl_xor_sync(0xffffffffu, pvsq, 1);
    pvsq += __shfl_xor_sync(0xffffffffu, pvsq, 2);
    const float inv = (pvsq > 0.f) ? rsqrtf(pvsq) : 0.f;  /* |v|=0 -> vhat=0 -> cos=0 (matches ref) */

    g_hx[(size_t)cell * 4 + r] = pack8h(x[0],x[1],x[2],x[3],x[4],x[5],x[6],x[7]);
    g_hv[(size_t)cell * 4 + r] = pack8h(v[0]*inv, v[1]*inv, v[2]*inv, v[3]*inv,
                                        v[4]*inv, v[5]*inv, v[6]*inv, v[7]*inv);
}

__device__ __forceinline__ void as_h2(const float4 w, __half2* h)
{
    unsigned a0 = __float_as_uint(w.x), a1 = __float_as_uint(w.y);
    unsigned a2 = __float_as_uint(w.z), a3 = __float_as_uint(w.w);
    h[0] = *reinterpret_cast<__half2*>(&a0);
    h[1] = *reinterpret_cast<__half2*>(&a1);
    h[2] = *reinterpret_cast<__half2*>(&a2);
    h[3] = *reinterpret_cast<__half2*>(&a3);
}

__global__ __launch_bounds__(THREADS, BLOCKS_PER_SM) void cost_kernel(
    const int* __restrict__ idx,
    float* __restrict__ out)
{
    const int warp  = threadIdx.x >> 5;
    const int lane  = threadIdx.x & 31;
    const int gwarp = blockIdx.x * WARPS_PER_BLOCK + warp;
    const int r     = lane & 3;          /* 16B slice within a 64B row */
    const int nb    = lane >> 2;         /* neighbor sub-slot (0..7) per batch */

    __shared__ float ws[WARPS_PER_BLOCK];
    __shared__ int   s_islast;

    float lsum = 0.0f;

    for (int cell = gwarp; cell < N_CELLS; cell += TOTAL_WARPS) {
        /* Own slices as raw half2 (zero conversions). u-dim = component 0 of slice 0. */
        __half2 a[4], vh[4];
        as_h2(g_hx[(size_t)cell * 4 + r], a);
        as_h2(g_hv[(size_t)cell * 4 + r], vh);

        const int ib = cell * KP1 + 1;

        /* Front-issue all four gathers (independent; one LDG.128 covers 8 full rows). */
        const int j0 = idx[ib + (0  + nb)];
        const int j1 = idx[ib + (8  + nb)];
        const int j2 = idx[ib + (16 + nb)];
        const int j3 = idx[ib + ((24 + nb < KP1 - 1) ? 24 + nb : KP1 - 2)];
        const float4 w0 = g_hx[(size_t)j0 * 4 + r];
        const float4 w1 = g_hx[(size_t)j1 * 4 + r];
        const float4 w2 = g_hx[(size_t)j2 * 4 + r];
        const float4 w3 = g_hx[(size_t)j3 * 4 + r];

        float cmax = -3.0e38f;

        #pragma unroll
        for (int bt = 0; bt < 4; bt++) {
            const float4 w = (bt == 0) ? w0 : (bt == 1) ? w1 : (bt == 2) ? w2 : w3;
            const int slot = bt * 8 + nb;

            __half2 n[4];
            as_h2(w, n);

            /* d = n - a; dot with vhat and with itself, all in HFMA2. */
            const __half2 d0 = __hsub2(n[0], a[0]);
            const __half2 d1 = __hsub2(n[1], a[1]);
            const __half2 d2 = __hsub2(n[2], a[2]);
            const __half2 d3 = __hsub2(n[3], a[3]);

            __half2 ad = __hmul2(vh[0], d0);
            ad = __hfma2(vh[1], d1, ad);
            ad = __hfma2(vh[2], d2, ad);
            ad = __hfma2(vh[3], d3, ad);

            __half2 an = __hmul2(d0, d0);
            an = __hfma2(d1, d1, an);
            an = __hfma2(d2, d2, an);
            an = __hfma2(d3, d3, an);

            const float2 fd = __half22float2(ad);
            const float2 fn = __half22float2(an);
            float pd = fd.x + fd.y;
            float pn = fn.x + fn.y;

            /* Quad reduce (2 levels within aligned groups of 4). */
            pd += __shfl_xor_sync(0xffffffffu, pd, 1);
            pd += __shfl_xor_sync(0xffffffffu, pd, 2);
            pn += __shfl_xor_sync(0xffffffffu, pn, 1);
            pn += __shfl_xor_sync(0xffffffffu, pn, 2);

            if (r == 0 && slot < KP1 - 1) {
                const float c = (pn > 0.f) ? pd * rsqrtf(pn) : 0.f;  /* vn=0 -> cos=0 */
                cmax = fmaxf(cmax, c);
            }
        }

        /* Leaders at lanes 0,4,...,28 -> xor4/8/16 completes the warp max. */
        cmax = fmaxf(cmax, __shfl_xor_sync(0xffffffffu, cmax, 4));
        cmax = fmaxf(cmax, __shfl_xor_sync(0xffffffffu, cmax, 8));
        cmax = fmaxf(cmax, __shfl_xor_sync(0xffffffffu, cmax, 16));

        if (lane == 0) lsum += 1.0f - cmax;
    }

    if (lane == 0) ws[warp] = lsum;
    __syncthreads();

    if (threadIdx.x == 0) {
        float bsum = 0.0f;
        #pragma unroll
        for (int w = 0; w < WARPS_PER_BLOCK; w++) bsum += ws[w];
        g_partials[blockIdx.x] = bsum;
        __threadfence();
        const unsigned t = atomicInc(&g_ticket, GRID - 1);  /* wraps -> graph-replay safe */
        s_islast = (t == GRID - 1);
    }
    __syncthreads();

    if (s_islast) {
        float psum = 0.0f;
        const volatile float* vp = g_partials;
        for (int i = threadIdx.x; i < GRID; i += THREADS) psum += vp[i];
        #pragma unroll
        for (int o = 16; o > 0; o >>= 1)
            psum += __shfl_xor_sync(0xffffffffu, psum, o);
        if (lane == 0) ws[warp] = psum;
        __syncthreads();
        if (threadIdx.x == 0) {
            float total = 0.0f;
            #pragma unroll
            for (int w = 0; w < WARPS_PER_BLOCK; w++) total += ws[w];
            out[0] = total * (1.0f / (float)N_CELLS);
        }
    }
}

extern "C" void kernel_launch(void* const* d_in, const int* in_sizes, int n_in,
                              void* d_out, int out_size) {
    const float* u   = (const float*)d_in[0];
    const float* s   = (const float*)d_in[1];
    const float* up  = (const float*)d_in[2];
    const float* sp  = (const float*)d_in[3];
    const int*   idx = (const int*)d_in[4];
    float* out = (float*)d_out;

    pack_kernel<<<(N_CELLS * 4 + THREADS - 1) / THREADS, THREADS>>>(u, s, up, sp);
    cost_kernel<<<GRID, THREADS>>>(idx, out);
}